// round 4
// baseline (speedup 1.0000x reference)
#include <cuda_runtime.h>
#include <cstdint>

// Problem shape (fixed by the reference): B=4, N=M=8192, D=3, fp32.
#define BATCH     4
#define NPTS      8192
#define YTILE     512              // y points per smem tile
#define PAIRS     (YTILE / 2)      // packed y-pairs per tile
#define THREADS   128
#define IX        4                // x points per thread
#define XPERCTA   (THREADS * IX)   // 512
#define XCHUNKS   (NPTS / XPERCTA) // 16
#define YCHUNKS   (NPTS / YTILE)   // 16
#define GRID      (BATCH * XCHUNKS * YCHUNKS)  // 1024
#define TOTKEY    (2 * BATCH * NPTS)           // 65536: rows then cols
#define INF_BITS  0x7f800000u
#define SUMA_CTAS    64
#define SUMA_THREADS 256

// Cross-CTA combine scratch, zero-initialized at module load.
// key = INF_BITS - float_bits(dist), dist clamped >= 0. atomicMax(key) == min(dist).
// key >= 1 for any valid dist, 0 == "empty". sum stage re-zeros for next replay.
__device__ unsigned int g_acc[TOTKEY];
__device__ float        g_part[SUMA_CTAS];

typedef unsigned long long u64;

__device__ __forceinline__ u64 pk_ff(float lo, float hi) {
    u64 r;
    asm("mov.b64 %0, {%1,%2};" : "=l"(r) : "f"(lo), "f"(hi));
    return r;
}

// Full packed distance of one x against a y-pair (both halves):
//   d = (x2 + nn) - 2*(x0*y0 + x1*y1 + x2*y2)
__device__ __forceinline__ void dist2(float& lo, float& hi,
    u64 c0, u64 c1, u64 c2, u64 xx,
    u64 y0, u64 y1, u64 y2, u64 nn)
{
    asm("{\n\t"
        ".reg .b64 t;\n\t"
        "add.rn.f32x2 t, %5, %9;\n\t"
        "fma.rn.f32x2 t, %2, %6, t;\n\t"
        "fma.rn.f32x2 t, %3, %7, t;\n\t"
        "fma.rn.f32x2 t, %4, %8, t;\n\t"
        "mov.b64 {%0, %1}, t;\n\t"
        "}"
        : "=f"(lo), "=f"(hi)
        : "l"(c0), "l"(c1), "l"(c2), "l"(xx),
          "l"(y0), "l"(y1), "l"(y2), "l"(nn));
}

__device__ __forceinline__ float warp_min(float v) {
#pragma unroll
    for (int k = 16; k > 0; k >>= 1)
        v = fminf(v, __shfl_xor_sync(0xffffffffu, v, k));
    return v;
}

__device__ __forceinline__ unsigned int key_of(float d) {
    return INF_BITS - __float_as_uint(fmaxf(d, 0.0f));
}

// ---------------- main: dedup'd row-min + col-min over a tile ----------------
__global__ void __launch_bounds__(THREADS)
chamfer_min_kernel(const float* __restrict__ x, const float* __restrict__ y) {
    // smem layout per pair p (32 bytes): [y0a y0b | y1a y1b | y2a y2b | nna nnb]
    __shared__ __align__(16) float sh[YTILE * 4];

    const int cta = blockIdx.x;
    const int yc  = cta & (YCHUNKS - 1);
    const int xc  = (cta >> 4) & (XCHUNKS - 1);
    const int b   = cta >> 8;

    // ---- cooperative fill of the y tile (with precomputed ||y||^2) ----
    const float* dbase = y + ((size_t)b * NPTS + (size_t)yc * YTILE) * 3;
    for (int m = threadIdx.x; m < YTILE; m += THREADS) {
        float a0 = dbase[m * 3 + 0];
        float a1 = dbase[m * 3 + 1];
        float a2 = dbase[m * 3 + 2];
        float nn = fmaf(a0, a0, fmaf(a1, a1, a2 * a2));
        int p = m >> 1, h = m & 1;
        float* s = sh + p * 8 + h;
        s[0] = a0; s[2] = a1; s[4] = a2; s[6] = nn;
    }
    __syncthreads();

    // ---- per-thread x points: coefficients (-2x) and x^2, packed broadcast ----
    const float* sbase = x + ((size_t)b * NPTS + (size_t)xc * XPERCTA) * 3;
    u64 C0[IX], C1[IX], C2[IX], XX[IX];
    float rlo[IX], rhi[IX];
#pragma unroll
    for (int i = 0; i < IX; i++) {
        int xi = threadIdx.x + i * THREADS;
        float a0 = sbase[xi * 3 + 0];
        float a1 = sbase[xi * 3 + 1];
        float a2 = sbase[xi * 3 + 2];
        float x2 = fmaf(a0, a0, fmaf(a1, a1, a2 * a2));
        C0[i] = pk_ff(-2.0f * a0, -2.0f * a0);
        C1[i] = pk_ff(-2.0f * a1, -2.0f * a1);
        C2[i] = pk_ff(-2.0f * a2, -2.0f * a2);
        XX[i] = pk_ff(x2, x2);
        rlo[i] = 3.0e38f;
        rhi[i] = 3.0e38f;
    }

    const bool lane0 = (threadIdx.x & 31) == 0;
    const int colbase = BATCH * NPTS + b * NPTS + yc * YTILE;
    const ulonglong2* shp = (const ulonglong2*)sh;

    // ---- inner loop: each dist feeds BOTH row-min and col-min ----
#pragma unroll 8
    for (int p = 0; p < PAIRS; ++p) {
        ulonglong2 va = shp[2 * p + 0];  // y0 pair, y1 pair
        ulonglong2 vb = shp[2 * p + 1];  // y2 pair, nn pair
        float dlo[IX], dhi[IX];
#pragma unroll
        for (int i = 0; i < IX; i++) {
            dist2(dlo[i], dhi[i], C0[i], C1[i], C2[i], XX[i], va.x, va.y, vb.x, vb.y);
            rlo[i] = fminf(rlo[i], dlo[i]);
            rhi[i] = fminf(rhi[i], dhi[i]);
        }
        // col-min over this thread's IX x's, then across the warp
        float cl = fminf(fminf(dlo[0], dlo[1]), fminf(dlo[2], dlo[3]));
        float ch = fminf(fminf(dhi[0], dhi[1]), fminf(dhi[2], dhi[3]));
        cl = warp_min(cl);
        ch = warp_min(ch);
        if (lane0) {
            atomicMax(&g_acc[colbase + 2 * p + 0], key_of(cl));
            atomicMax(&g_acc[colbase + 2 * p + 1], key_of(ch));
        }
    }

    // ---- flush row minima ----
#pragma unroll
    for (int i = 0; i < IX; i++) {
        float m = fminf(rlo[i], rhi[i]);
        int idx = b * NPTS + xc * XPERCTA + i * THREADS + threadIdx.x;
        atomicMax(&g_acc[idx], key_of(m));
    }
}

// ---------------- stage A: 64-CTA deterministic partial sums + re-zero ----------------
__global__ void chamfer_sumA_kernel() {
    __shared__ float red[SUMA_THREADS];
    // Each CTA owns 1024 keys = 256 uint4; one uint4 per thread.
    uint4* gp = (uint4*)g_acc;
    int idx = blockIdx.x * SUMA_THREADS + threadIdx.x;
    uint4 v = gp[idx];
    float s = __uint_as_float(INF_BITS - v.x)
            + __uint_as_float(INF_BITS - v.y)
            + __uint_as_float(INF_BITS - v.z)
            + __uint_as_float(INF_BITS - v.w);
    gp[idx] = make_uint4(0u, 0u, 0u, 0u);   // reset for next replay
    red[threadIdx.x] = s;
    __syncthreads();
    for (int k = SUMA_THREADS / 2; k > 0; k >>= 1) {
        if (threadIdx.x < k) red[threadIdx.x] += red[threadIdx.x + k];
        __syncthreads();
    }
    if (threadIdx.x == 0) g_part[blockIdx.x] = red[0];
}

// ---------------- stage B: combine 64 partials + scale ----------------
__global__ void chamfer_sumB_kernel(float* __restrict__ out) {
    __shared__ float red[SUMA_CTAS];
    red[threadIdx.x] = g_part[threadIdx.x];
    __syncthreads();
    for (int k = SUMA_CTAS / 2; k > 0; k >>= 1) {
        if (threadIdx.x < k) red[threadIdx.x] += red[threadIdx.x + k];
        __syncthreads();
    }
    if (threadIdx.x == 0)
        out[0] = red[0] * (1.0f / (float)(BATCH * NPTS));
}

extern "C" void kernel_launch(void* const* d_in, const int* in_sizes, int n_in,
                              void* d_out, int out_size) {
    const float* x = (const float*)d_in[0];
    const float* y = (const float*)d_in[1];
    float* out = (float*)d_out;
    (void)in_sizes; (void)n_in; (void)out_size;

    chamfer_min_kernel<<<GRID, THREADS>>>(x, y);
    chamfer_sumA_kernel<<<SUMA_CTAS, SUMA_THREADS>>>();
    chamfer_sumB_kernel<<<1, SUMA_CTAS>>>(out);
}

// round 5
// speedup vs baseline: 1.1684x; 1.1684x over previous
#include <cuda_runtime.h>
#include <cstdint>

// Problem shape (fixed by the reference): B=4, N=M=8192, D=3, fp32.
#define BATCH     4
#define NPTS      8192
#define YTILE     1024             // tile points per smem tile
#define PAIRS     (YTILE / 2)      // packed pairs per tile
#define THREADS   128
#define IX        4                // register points per thread
#define XPERCTA   (THREADS * IX)   // 512
#define XCHUNKS   (NPTS / XPERCTA) // 16
#define YCHUNKS   (NPTS / YTILE)   // 8
#define GRID      (2 * BATCH * XCHUNKS * YCHUNKS)  // 1024
#define TOTKEY    (2 * BATCH * NPTS)               // 65536
#define INF_BITS  0x7f800000u
#define SUMA_CTAS    64
#define SUMA_THREADS 256

// Cross-CTA combine scratch, zero-initialized at module load.
// key = INF_BITS - float_bits(dist), dist clamped >= 0. atomicMax(key) == min(dist).
// key >= 1 for any valid dist, 0 == "empty". Sum stage re-zeros for next replay.
__device__ unsigned int g_acc[TOTKEY];
__device__ float        g_part[SUMA_CTAS];

typedef unsigned long long u64;

__device__ __forceinline__ u64 pk_ff(float lo, float hi) {
    u64 r;
    asm("mov.b64 %0, {%1,%2};" : "=l"(r) : "f"(lo), "f"(hi));
    return r;
}

// One packed candidate: t = nn - 2*(x.y) for two tile points at once,
// folded straight into the two running minima. 3 fma2 + 2 min, no movs
// (ptxas aliases the b64 halves).
__device__ __forceinline__ void step(float& mlo, float& mhi,
    u64 c0, u64 c1, u64 c2, u64 y0, u64 y1, u64 y2, u64 nn)
{
    asm("{\n\t"
        ".reg .b64 t;\n\t"
        ".reg .f32 lo, hi;\n\t"
        "fma.rn.f32x2 t, %2, %5, %8;\n\t"
        "fma.rn.f32x2 t, %3, %6, t;\n\t"
        "fma.rn.f32x2 t, %4, %7, t;\n\t"
        "mov.b64 {lo, hi}, t;\n\t"
        "min.f32 %0, %0, lo;\n\t"
        "min.f32 %1, %1, hi;\n\t"
        "}"
        : "+f"(mlo), "+f"(mhi)
        : "l"(c0), "l"(c1), "l"(c2), "l"(y0), "l"(y1), "l"(y2), "l"(nn));
}

// ---------------- main: per-point min over a tile (one direction per CTA) ----------------
__global__ void __launch_bounds__(THREADS)
chamfer_min_kernel(const float* __restrict__ x, const float* __restrict__ y) {
    // smem per pair p (32 bytes): [y0a y0b | y1a y1b | y2a y2b | nna nnb]
    __shared__ __align__(16) float sh[YTILE * 4];

    const int cta = blockIdx.x;
    const int yc  = cta & (YCHUNKS - 1);
    const int xc  = (cta >> 3) & (XCHUNKS - 1);
    const int b   = (cta >> 7) & (BATCH - 1);
    const int dir = (cta >> 9) & 1;

    const float* src = dir ? y : x;  // points we minimize FOR (register side)
    const float* dst = dir ? x : y;  // points we search over (smem side)

    // ---- cooperative fill of the tile (with precomputed ||p||^2) ----
    const float* dbase = dst + ((size_t)b * NPTS + (size_t)yc * YTILE) * 3;
    for (int m = threadIdx.x; m < YTILE; m += THREADS) {
        float a0 = dbase[m * 3 + 0];
        float a1 = dbase[m * 3 + 1];
        float a2 = dbase[m * 3 + 2];
        float nn = fmaf(a0, a0, fmaf(a1, a1, a2 * a2));
        int p = m >> 1, h = m & 1;
        float* s = sh + p * 8 + h;
        s[0] = a0; s[2] = a1; s[4] = a2; s[6] = nn;
    }
    __syncthreads();

    // ---- per-thread register points: packed coefficients (-2x) ----
    const float* sbase = src + ((size_t)b * NPTS + (size_t)xc * XPERCTA) * 3;
    u64 C0[IX], C1[IX], C2[IX];
    float x2v[IX], mnlo[IX], mnhi[IX];
#pragma unroll
    for (int i = 0; i < IX; i++) {
        int xi = threadIdx.x + i * THREADS;
        float a0 = sbase[xi * 3 + 0];
        float a1 = sbase[xi * 3 + 1];
        float a2 = sbase[xi * 3 + 2];
        x2v[i] = fmaf(a0, a0, fmaf(a1, a1, a2 * a2));
        C0[i] = pk_ff(-2.0f * a0, -2.0f * a0);
        C1[i] = pk_ff(-2.0f * a1, -2.0f * a1);
        C2[i] = pk_ff(-2.0f * a2, -2.0f * a2);
        mnlo[i] = 3.0e38f;
        mnhi[i] = 3.0e38f;
    }

    // ---- inner loop: 2 LDS.128 + 12 fma2 + 8 FMNMX per 256 warp-evals ----
    const ulonglong2* shp = (const ulonglong2*)sh;
#pragma unroll 8
    for (int p = 0; p < PAIRS; ++p) {
        ulonglong2 va = shp[2 * p + 0];  // y0 pair, y1 pair
        ulonglong2 vb = shp[2 * p + 1];  // y2 pair, nn pair
#pragma unroll
        for (int i = 0; i < IX; i++)
            step(mnlo[i], mnhi[i], C0[i], C1[i], C2[i], va.x, va.y, vb.x, vb.y);
    }

    // ---- combine halves, add ||x||^2, clamp, cross-CTA combine ----
#pragma unroll
    for (int i = 0; i < IX; i++) {
        float m = fminf(mnlo[i], mnhi[i]);
        float dist = fmaxf(x2v[i] + m, 0.0f);   // non-negative by construction
        int idx = (dir * BATCH + b) * NPTS + xc * XPERCTA + i * THREADS + threadIdx.x;
        atomicMax(&g_acc[idx], INF_BITS - __float_as_uint(dist));
    }
}

// ---------------- stage A: 64-CTA deterministic partial sums + re-zero ----------------
__global__ void chamfer_sumA_kernel() {
    __shared__ float red[SUMA_THREADS];
    uint4* gp = (uint4*)g_acc;
    int idx = blockIdx.x * SUMA_THREADS + threadIdx.x;
    uint4 v = gp[idx];
    float s = __uint_as_float(INF_BITS - v.x)
            + __uint_as_float(INF_BITS - v.y)
            + __uint_as_float(INF_BITS - v.z)
            + __uint_as_float(INF_BITS - v.w);
    gp[idx] = make_uint4(0u, 0u, 0u, 0u);   // reset for next replay
    red[threadIdx.x] = s;
    __syncthreads();
    for (int k = SUMA_THREADS / 2; k > 0; k >>= 1) {
        if (threadIdx.x < k) red[threadIdx.x] += red[threadIdx.x + k];
        __syncthreads();
    }
    if (threadIdx.x == 0) g_part[blockIdx.x] = red[0];
}

// ---------------- stage B: combine 64 partials + scale ----------------
__global__ void chamfer_sumB_kernel(float* __restrict__ out) {
    __shared__ float red[SUMA_CTAS];
    red[threadIdx.x] = g_part[threadIdx.x];
    __syncthreads();
    for (int k = SUMA_CTAS / 2; k > 0; k >>= 1) {
        if (threadIdx.x < k) red[threadIdx.x] += red[threadIdx.x + k];
        __syncthreads();
    }
    if (threadIdx.x == 0)
        out[0] = red[0] * (1.0f / (float)(BATCH * NPTS));
}

extern "C" void kernel_launch(void* const* d_in, const int* in_sizes, int n_in,
                              void* d_out, int out_size) {
    const float* x = (const float*)d_in[0];
    const float* y = (const float*)d_in[1];
    float* out = (float*)d_out;
    (void)in_sizes; (void)n_in; (void)out_size;

    chamfer_min_kernel<<<GRID, THREADS>>>(x, y);
    chamfer_sumA_kernel<<<SUMA_CTAS, SUMA_THREADS>>>();
    chamfer_sumB_kernel<<<1, SUMA_CTAS>>>(out);
}

// round 6
// speedup vs baseline: 1.1994x; 1.0265x over previous
#include <cuda_runtime.h>
#include <cstdint>

// Problem shape (fixed by the reference): B=4, N=M=8192, D=3, fp32.
#define BATCH     4
#define NPTS      8192
#define YTILE     512              // tile points per smem tile
#define PAIRS     (YTILE / 2)      // packed pairs per tile
#define THREADS   128
#define IX        4                // register points per thread
#define XPERCTA   (THREADS * IX)   // 512
#define XCHUNKS   (NPTS / XPERCTA) // 16
#define YCHUNKS   (NPTS / YTILE)   // 16
#define GRID      (2 * BATCH * XCHUNKS * YCHUNKS)  // 2048
#define TOTKEY    (2 * BATCH * NPTS)               // 65536
#define INF_BITS  0x7f800000u
#define SUMA_CTAS    64
#define SUMA_THREADS 256

// Cross-CTA combine scratch, zero-initialized at module load.
// key = INF_BITS - float_bits(dist), dist clamped >= 0. atomicMax(key) == min(dist).
// key >= 1 for any valid dist, 0 == "empty". Sum stage re-zeros for next replay.
__device__ unsigned int g_acc[TOTKEY];
__device__ float        g_part[SUMA_CTAS];

typedef unsigned long long u64;

__device__ __forceinline__ u64 pk_ff(float lo, float hi) {
    u64 r;
    asm("mov.b64 %0, {%1,%2};" : "=l"(r) : "f"(lo), "f"(hi));
    return r;
}

// One packed candidate: t = nn - 2*(x.y) for two tile points at once,
// folded straight into the two running minima. 3 fma2 + 2 min, no movs
// (ptxas aliases the b64 halves).
__device__ __forceinline__ void step(float& mlo, float& mhi,
    u64 c0, u64 c1, u64 c2, u64 y0, u64 y1, u64 y2, u64 nn)
{
    asm("{\n\t"
        ".reg .b64 t;\n\t"
        ".reg .f32 lo, hi;\n\t"
        "fma.rn.f32x2 t, %2, %5, %8;\n\t"
        "fma.rn.f32x2 t, %3, %6, t;\n\t"
        "fma.rn.f32x2 t, %4, %7, t;\n\t"
        "mov.b64 {lo, hi}, t;\n\t"
        "min.f32 %0, %0, lo;\n\t"
        "min.f32 %1, %1, hi;\n\t"
        "}"
        : "+f"(mlo), "+f"(mhi)
        : "l"(c0), "l"(c1), "l"(c2), "l"(y0), "l"(y1), "l"(y2), "l"(nn));
}

// ---------------- main: per-point min over a tile (one direction per CTA) ----------------
__global__ void __launch_bounds__(THREADS)
chamfer_min_kernel(const float* __restrict__ x, const float* __restrict__ y) {
    // smem per pair p (32 bytes): [y0a y0b | y1a y1b | y2a y2b | nna nnb]
    __shared__ __align__(16) float sh[YTILE * 4];

    const int cta = blockIdx.x;
    const int yc  = cta & (YCHUNKS - 1);
    const int xc  = (cta >> 4) & (XCHUNKS - 1);
    const int b   = (cta >> 8) & (BATCH - 1);
    const int dir = (cta >> 10) & 1;

    const float* src = dir ? y : x;  // points we minimize FOR (register side)
    const float* dst = dir ? x : y;  // points we search over (smem side)

    // ---- cooperative fill of the tile (with precomputed ||p||^2) ----
    const float* dbase = dst + ((size_t)b * NPTS + (size_t)yc * YTILE) * 3;
    for (int m = threadIdx.x; m < YTILE; m += THREADS) {
        float a0 = dbase[m * 3 + 0];
        float a1 = dbase[m * 3 + 1];
        float a2 = dbase[m * 3 + 2];
        float nn = fmaf(a0, a0, fmaf(a1, a1, a2 * a2));
        int p = m >> 1, h = m & 1;
        float* s = sh + p * 8 + h;
        s[0] = a0; s[2] = a1; s[4] = a2; s[6] = nn;
    }
    __syncthreads();

    // ---- per-thread register points: packed coefficients (-2x) ----
    const float* sbase = src + ((size_t)b * NPTS + (size_t)xc * XPERCTA) * 3;
    u64 C0[IX], C1[IX], C2[IX];
    float x2v[IX], mnlo[IX], mnhi[IX];
#pragma unroll
    for (int i = 0; i < IX; i++) {
        int xi = threadIdx.x + i * THREADS;
        float a0 = sbase[xi * 3 + 0];
        float a1 = sbase[xi * 3 + 1];
        float a2 = sbase[xi * 3 + 2];
        x2v[i] = fmaf(a0, a0, fmaf(a1, a1, a2 * a2));
        C0[i] = pk_ff(-2.0f * a0, -2.0f * a0);
        C1[i] = pk_ff(-2.0f * a1, -2.0f * a1);
        C2[i] = pk_ff(-2.0f * a2, -2.0f * a2);
        mnlo[i] = 3.0e38f;
        mnhi[i] = 3.0e38f;
    }

    // ---- inner loop: 2 LDS.128 + 12 fma2 + 8 FMNMX per 256 warp-evals ----
    const ulonglong2* shp = (const ulonglong2*)sh;
#pragma unroll 8
    for (int p = 0; p < PAIRS; ++p) {
        ulonglong2 va = shp[2 * p + 0];  // y0 pair, y1 pair
        ulonglong2 vb = shp[2 * p + 1];  // y2 pair, nn pair
#pragma unroll
        for (int i = 0; i < IX; i++)
            step(mnlo[i], mnhi[i], C0[i], C1[i], C2[i], va.x, va.y, vb.x, vb.y);
    }

    // ---- combine halves, add ||x||^2, clamp, cross-CTA combine ----
#pragma unroll
    for (int i = 0; i < IX; i++) {
        float m = fminf(mnlo[i], mnhi[i]);
        float dist = fmaxf(x2v[i] + m, 0.0f);   // non-negative by construction
        int idx = (dir * BATCH + b) * NPTS + xc * XPERCTA + i * THREADS + threadIdx.x;
        atomicMax(&g_acc[idx], INF_BITS - __float_as_uint(dist));
    }
}

// ---------------- stage A: 64-CTA deterministic partial sums + re-zero ----------------
__global__ void chamfer_sumA_kernel() {
    __shared__ float red[SUMA_THREADS];
    uint4* gp = (uint4*)g_acc;
    int idx = blockIdx.x * SUMA_THREADS + threadIdx.x;
    uint4 v = gp[idx];
    float s = __uint_as_float(INF_BITS - v.x)
            + __uint_as_float(INF_BITS - v.y)
            + __uint_as_float(INF_BITS - v.z)
            + __uint_as_float(INF_BITS - v.w);
    gp[idx] = make_uint4(0u, 0u, 0u, 0u);   // reset for next replay
    red[threadIdx.x] = s;
    __syncthreads();
    for (int k = SUMA_THREADS / 2; k > 0; k >>= 1) {
        if (threadIdx.x < k) red[threadIdx.x] += red[threadIdx.x + k];
        __syncthreads();
    }
    if (threadIdx.x == 0) g_part[blockIdx.x] = red[0];
}

// ---------------- stage B: combine 64 partials + scale ----------------
__global__ void chamfer_sumB_kernel(float* __restrict__ out) {
    __shared__ float red[SUMA_CTAS];
    red[threadIdx.x] = g_part[threadIdx.x];
    __syncthreads();
    for (int k = SUMA_CTAS / 2; k > 0; k >>= 1) {
        if (threadIdx.x < k) red[threadIdx.x] += red[threadIdx.x + k];
        __syncthreads();
    }
    if (threadIdx.x == 0)
        out[0] = red[0] * (1.0f / (float)(BATCH * NPTS));
}

extern "C" void kernel_launch(void* const* d_in, const int* in_sizes, int n_in,
                              void* d_out, int out_size) {
    const float* x = (const float*)d_in[0];
    const float* y = (const float*)d_in[1];
    float* out = (float*)d_out;
    (void)in_sizes; (void)n_in; (void)out_size;

    chamfer_min_kernel<<<GRID, THREADS>>>(x, y);
    chamfer_sumA_kernel<<<SUMA_CTAS, SUMA_THREADS>>>();
    chamfer_sumB_kernel<<<1, SUMA_CTAS>>>(out);
}

// round 7
// speedup vs baseline: 1.2828x; 1.0695x over previous
#include <cuda_runtime.h>
#include <cstdint>

// Problem shape (fixed by the reference): B=4, N=M=8192, D=3, fp32.
#define BATCH     4
#define NPTS      8192
#define YTILE     512              // tile points per smem tile
#define PAIRS     (YTILE / 2)      // packed pairs per tile
#define THREADS   128
#define IX        4                // register points per thread
#define XPERCTA   (THREADS * IX)   // 512
#define XCHUNKS   (NPTS / XPERCTA) // 16
#define YCHUNKS   (NPTS / YTILE)   // 16
#define GRID      (2 * BATCH * XCHUNKS * YCHUNKS)  // 2048
#define TOTKEY    (2 * BATCH * NPTS)               // 65536
#define INF_BITS  0x7f800000u
#define SUMA_CTAS    64
#define SUMA_THREADS 256

// Cross-CTA combine scratch, zero-initialized at module load.
// key = INF_BITS - float_bits(dist), dist clamped >= 0. atomicMax(key) == min(dist).
// key >= 1 for any valid dist, 0 == "empty". Sum stage re-zeros for next replay.
__device__ unsigned int g_acc[TOTKEY];
__device__ float        g_part[SUMA_CTAS];

typedef unsigned long long u64;

__device__ __forceinline__ u64 pk_ff(float lo, float hi) {
    u64 r;
    asm("mov.b64 %0, {%1,%2};" : "=l"(r) : "f"(lo), "f"(hi));
    return r;
}

// One packed candidate: t = nn - 2*(x.y) for two tile points at once,
// folded straight into the two running minima. 3 fma2 + 2 min.
__device__ __forceinline__ void step(float& mlo, float& mhi,
    u64 c0, u64 c1, u64 c2, u64 y0, u64 y1, u64 y2, u64 nn)
{
    asm("{\n\t"
        ".reg .b64 t;\n\t"
        ".reg .f32 lo, hi;\n\t"
        "fma.rn.f32x2 t, %2, %5, %8;\n\t"
        "fma.rn.f32x2 t, %3, %6, t;\n\t"
        "fma.rn.f32x2 t, %4, %7, t;\n\t"
        "mov.b64 {lo, hi}, t;\n\t"
        "min.f32 %0, %0, lo;\n\t"
        "min.f32 %1, %1, hi;\n\t"
        "}"
        : "+f"(mlo), "+f"(mhi)
        : "l"(c0), "l"(c1), "l"(c2), "l"(y0), "l"(y1), "l"(y2), "l"(nn));
}

// ---------------- main: per-point min over a tile (one direction per CTA) ----------------
__global__ void __launch_bounds__(THREADS, 8)
chamfer_min_kernel(const float* __restrict__ x, const float* __restrict__ y) {
    // smem per pair p (32 bytes): [y0a y0b | y1a y1b | y2a y2b | nna nnb]
    __shared__ __align__(16) float sh[YTILE * 4];

    const int cta = blockIdx.x;
    const int yc  = cta & (YCHUNKS - 1);
    const int xc  = (cta >> 4) & (XCHUNKS - 1);
    const int b   = (cta >> 8) & (BATCH - 1);
    const int dir = (cta >> 10) & 1;

    const float* src = dir ? y : x;  // points we minimize FOR (register side)
    const float* dst = dir ? x : y;  // points we search over (smem side)

    // ---- cooperative fill of the tile (with precomputed ||p||^2) ----
    const float* dbase = dst + ((size_t)b * NPTS + (size_t)yc * YTILE) * 3;
    for (int m = threadIdx.x; m < YTILE; m += THREADS) {
        float a0 = dbase[m * 3 + 0];
        float a1 = dbase[m * 3 + 1];
        float a2 = dbase[m * 3 + 2];
        float nn = fmaf(a0, a0, fmaf(a1, a1, a2 * a2));
        int p = m >> 1, h = m & 1;
        float* s = sh + p * 8 + h;
        s[0] = a0; s[2] = a1; s[4] = a2; s[6] = nn;
    }
    __syncthreads();

    // ---- per-thread register points: packed coefficients (-2x) ----
    const float* sbase = src + ((size_t)b * NPTS + (size_t)xc * XPERCTA) * 3;
    u64 C0[IX], C1[IX], C2[IX];
    float x2v[IX], mnlo[IX], mnhi[IX];
#pragma unroll
    for (int i = 0; i < IX; i++) {
        int xi = threadIdx.x + i * THREADS;
        float a0 = sbase[xi * 3 + 0];
        float a1 = sbase[xi * 3 + 1];
        float a2 = sbase[xi * 3 + 2];
        x2v[i] = fmaf(a0, a0, fmaf(a1, a1, a2 * a2));
        C0[i] = pk_ff(-2.0f * a0, -2.0f * a0);
        C1[i] = pk_ff(-2.0f * a1, -2.0f * a1);
        C2[i] = pk_ff(-2.0f * a2, -2.0f * a2);
        mnlo[i] = 3.0e38f;
        mnhi[i] = 3.0e38f;
    }

    // ---- inner loop: manually double-buffered so the LDS for pair p+1
    //      overlaps the 12-cyc fma chain of pair p ----
    const ulonglong2* shp = (const ulonglong2*)sh;
    ulonglong2 va = shp[0];          // y0 pair, y1 pair
    ulonglong2 vb = shp[1];          // y2 pair, nn pair
#pragma unroll 4
    for (int p = 0; p < PAIRS - 1; ++p) {
        ulonglong2 na = shp[2 * p + 2];
        ulonglong2 nb = shp[2 * p + 3];
#pragma unroll
        for (int i = 0; i < IX; i++)
            step(mnlo[i], mnhi[i], C0[i], C1[i], C2[i], va.x, va.y, vb.x, vb.y);
        va = na; vb = nb;
    }
#pragma unroll
    for (int i = 0; i < IX; i++)      // last pair
        step(mnlo[i], mnhi[i], C0[i], C1[i], C2[i], va.x, va.y, vb.x, vb.y);

    // ---- combine halves, add ||x||^2, clamp, cross-CTA combine ----
#pragma unroll
    for (int i = 0; i < IX; i++) {
        float m = fminf(mnlo[i], mnhi[i]);
        float dist = fmaxf(x2v[i] + m, 0.0f);   // non-negative by construction
        int idx = (dir * BATCH + b) * NPTS + xc * XPERCTA + i * THREADS + threadIdx.x;
        atomicMax(&g_acc[idx], INF_BITS - __float_as_uint(dist));
    }
}

// ---------------- stage A: 64-CTA deterministic partial sums + re-zero ----------------
__global__ void chamfer_sumA_kernel() {
    __shared__ float red[SUMA_THREADS];
    uint4* gp = (uint4*)g_acc;
    int idx = blockIdx.x * SUMA_THREADS + threadIdx.x;
    uint4 v = gp[idx];
    float s = __uint_as_float(INF_BITS - v.x)
            + __uint_as_float(INF_BITS - v.y)
            + __uint_as_float(INF_BITS - v.z)
            + __uint_as_float(INF_BITS - v.w);
    gp[idx] = make_uint4(0u, 0u, 0u, 0u);   // reset for next replay
    red[threadIdx.x] = s;
    __syncthreads();
    for (int k = SUMA_THREADS / 2; k > 0; k >>= 1) {
        if (threadIdx.x < k) red[threadIdx.x] += red[threadIdx.x + k];
        __syncthreads();
    }
    if (threadIdx.x == 0) g_part[blockIdx.x] = red[0];
}

// ---------------- stage B: combine 64 partials + scale ----------------
__global__ void chamfer_sumB_kernel(float* __restrict__ out) {
    __shared__ float red[SUMA_CTAS];
    red[threadIdx.x] = g_part[threadIdx.x];
    __syncthreads();
    for (int k = SUMA_CTAS / 2; k > 0; k >>= 1) {
        if (threadIdx.x < k) red[threadIdx.x] += red[threadIdx.x + k];
        __syncthreads();
    }
    if (threadIdx.x == 0)
        out[0] = red[0] * (1.0f / (float)(BATCH * NPTS));
}

extern "C" void kernel_launch(void* const* d_in, const int* in_sizes, int n_in,
                              void* d_out, int out_size) {
    const float* x = (const float*)d_in[0];
    const float* y = (const float*)d_in[1];
    float* out = (float*)d_out;
    (void)in_sizes; (void)n_in; (void)out_size;

    chamfer_min_kernel<<<GRID, THREADS>>>(x, y);
    chamfer_sumA_kernel<<<SUMA_CTAS, SUMA_THREADS>>>();
    chamfer_sumB_kernel<<<1, SUMA_CTAS>>>(out);
}